// round 3
// baseline (speedup 1.0000x reference)
#include <cuda_runtime.h>

#define THREADS 512
#define ITEMS 16
#define TILE (THREADS * ITEMS)   // 8192
#define MAX_TILES 65536
#define SIDX(i) ((i) + ((i) >> 4))   // smem skew: conflict-free blocked writes

// decoupled-lookback state: high 32 bits = status (0 invalid, 1 aggregate, 2 prefix),
// low 32 bits = fp32 value bits. One 64-bit atomic word => no fence needed.
__device__ unsigned long long g_state[MAX_TILES];
__device__ unsigned int g_ticket;

__global__ void rtam_init(int ntiles) {
    int i = blockIdx.x * blockDim.x + threadIdx.x;
    if (i < ntiles) g_state[i] = 0ULL;
    if (i == 0) g_ticket = 0u;
}

__device__ __forceinline__ unsigned long long pack_sv(unsigned st, float v) {
    return ((unsigned long long)st << 32) | (unsigned long long)__float_as_uint(v);
}

__global__ void __launch_bounds__(THREADS, 1) rtam_scan(
    const int* __restrict__ ann,
    const float* __restrict__ p_origin,
    const float* __restrict__ p_bd,
    const float* __restrict__ p_d,
    const float* __restrict__ p_s,
    const float* __restrict__ p_inc,
    const float* __restrict__ p_bi,
    float* __restrict__ out,
    int n)
{
    __shared__ float s_out[TILE + TILE / 16];   // skewed
    __shared__ float s_table[8];
    __shared__ float s_warp[THREADS / 32];
    __shared__ float s_excl;
    __shared__ unsigned s_tile;

    const int tid  = threadIdx.x;
    const int lane = tid & 31;
    const int wid  = tid >> 5;

    if (tid == 0) {
        s_tile = atomicAdd(&g_ticket, 1u);
        const float EPS = 0.05f;
        float bd = *p_bd, d = *p_d, s = *p_s, inc = *p_inc, bi = *p_bi;
        s_table[0] = 0.f;
        s_table[1] = fminf(bd, fminf(0.f, d)) - EPS;                 // big decrease
        s_table[2] = fminf(fmaxf(d, bd + EPS), -EPS);                // decrease (clip)
        s_table[3] = s;                                              // same
        s_table[4] = fminf(fmaxf(inc, EPS), bi - EPS);               // increase (clip)
        s_table[5] = fmaxf(bi, fmaxf(0.f, inc) + EPS);               // big increase
        s_table[6] = *p_origin;
    }
    __syncthreads();

    const unsigned tile = s_tile;
    const float origin  = s_table[6];
    const long long base = (long long)tile * TILE;
    const long long rem64 = (long long)n - base;
    const int remaining = (rem64 > (long long)TILE) ? TILE : (int)rem64;

    // ---- per-thread blocked load + serial inclusive scan (16 items) ----
    float vals[ITEMS];
    float run = 0.f;

    if (remaining >= TILE) {
        const int4* in4 = (const int4*)(ann + base);
        #pragma unroll
        for (int k = 0; k < ITEMS / 4; k++) {
            int4 c = in4[tid * (ITEMS / 4) + k];
            run += s_table[c.x]; vals[4 * k + 0] = run;
            run += s_table[c.y]; vals[4 * k + 1] = run;
            run += s_table[c.z]; vals[4 * k + 2] = run;
            run += s_table[c.w]; vals[4 * k + 3] = run;
        }
    } else {
        #pragma unroll
        for (int j = 0; j < ITEMS; j++) {
            long long idx = base + (long long)tid * ITEMS + j;
            float c = (idx < (long long)n) ? s_table[ann[idx]] : 0.f;
            run += c;
            vals[j] = run;
        }
    }

    // ---- block scan of per-thread sums (warp shfl + smem across 16 warps) ----
    const float tsum = run;
    float x = tsum;
    #pragma unroll
    for (int o = 1; o < 32; o <<= 1) {
        float y = __shfl_up_sync(0xFFFFFFFFu, x, o);
        if (lane >= o) x += y;
    }
    if (lane == 31) s_warp[wid] = x;
    __syncthreads();
    if (wid == 0) {
        float w = (lane < THREADS / 32) ? s_warp[lane] : 0.f;
        #pragma unroll
        for (int o = 1; o < THREADS / 32; o <<= 1) {
            float y = __shfl_up_sync(0xFFFFFFFFu, w, o);
            if (lane >= o) w += y;
        }
        if (lane < THREADS / 32) s_warp[lane] = w;
    }
    __syncthreads();

    const float block_agg   = s_warp[THREADS / 32 - 1];
    const float thread_excl = (wid > 0 ? s_warp[wid - 1] : 0.f) + (x - tsum);

    // ---- warp 0: publish aggregate, decoupled lookback, publish prefix ----
    if (wid == 0) {
        if (lane == 0)
            atomicExch(&g_state[tile], pack_sv(tile == 0 ? 2u : 1u, block_agg));

        float excl = 0.f;
        if (tile > 0) {
            int look = (int)tile - 1;
            for (;;) {
                int idx = look - lane;
                unsigned long long v = (idx >= 0) ? atomicAdd(&g_state[idx], 0ULL)
                                                  : pack_sv(2u, 0.f);
                unsigned st = (unsigned)(v >> 32);
                float val = __uint_as_float((unsigned)(v & 0xFFFFFFFFULL));
                unsigned pm = __ballot_sync(0xFFFFFFFFu, st == 2u);
                unsigned am = __ballot_sync(0xFFFFFFFFu, st >= 1u);
                if (pm) {
                    int p = __ffs(pm) - 1;   // closest predecessor with a full prefix
                    unsigned need = (p == 31) ? 0xFFFFFFFFu : ((1u << (p + 1)) - 1u);
                    if ((am & need) == need) {
                        float contrib = (lane <= p) ? val : 0.f;
                        #pragma unroll
                        for (int o = 16; o; o >>= 1)
                            contrib += __shfl_xor_sync(0xFFFFFFFFu, contrib, o);
                        excl += contrib;
                        break;
                    }
                } else if (am == 0xFFFFFFFFu) {
                    float contrib = val;     // window of 32 aggregates, keep walking
                    #pragma unroll
                    for (int o = 16; o; o >>= 1)
                        contrib += __shfl_xor_sync(0xFFFFFFFFu, contrib, o);
                    excl += contrib;
                    look -= 32;
                }
                // else: spin until predecessors publish
            }
            if (lane == 0)
                atomicExch(&g_state[tile], pack_sv(2u, excl + block_agg));
        }
        if (lane == 0) s_excl = excl;
    }

    // ---- stage tile-local results to skewed smem (overlaps lookback) ----
    #pragma unroll
    for (int j = 0; j < ITEMS; j++)
        s_out[SIDX(tid * ITEMS + j)] = thread_excl + vals[j];
    __syncthreads();

    const float ofs = origin + s_excl;

    // ---- coalesced, aligned store of out[base+1 .. base+remaining] ----
    if (remaining >= TILE) {
        float* op = out + base;                 // 16B-aligned (base % 8192 == 0)
        if (tid < 3)  op[1 + tid] = ofs + s_out[SIDX(tid)];       // head: out[base+1..3]
        if (tid == 3) op[TILE]    = ofs + s_out[SIDX(TILE - 1)];  // tail: out[base+TILE]
        float4* o4 = (float4*)(op + 4);         // 16B-aligned
        const int NV = (TILE - 4) / 4;          // 2047 vectors covering smem i = 3..8190
        for (int v = tid; v < NV; v += THREADS) {
            int i = 3 + 4 * v;
            float4 r;
            r.x = ofs + s_out[SIDX(i + 0)];
            r.y = ofs + s_out[SIDX(i + 1)];
            r.z = ofs + s_out[SIDX(i + 2)];
            r.w = ofs + s_out[SIDX(i + 3)];
            o4[v] = r;
        }
    } else {
        for (int i = tid; i < remaining; i += THREADS)
            out[base + 1 + i] = ofs + s_out[SIDX(i)];
    }

    if (tile == 0 && tid == 0) out[0] = origin;
}

extern "C" void kernel_launch(void* const* d_in, const int* in_sizes, int n_in,
                              void* d_out, int out_size) {
    const int*   ann    = (const int*)d_in[0];
    const float* origin = (const float*)d_in[1];
    const float* bd     = (const float*)d_in[2];
    const float* d      = (const float*)d_in[3];
    const float* s      = (const float*)d_in[4];
    const float* inc    = (const float*)d_in[5];
    const float* bi     = (const float*)d_in[6];
    float* out = (float*)d_out;

    int n = in_sizes[0];
    int ntiles = (n + TILE - 1) / TILE;
    if (ntiles > MAX_TILES) ntiles = MAX_TILES;   // (n = 2^25 -> 4096 tiles)

    rtam_init<<<(ntiles + 255) / 256, 256>>>(ntiles);
    rtam_scan<<<ntiles, THREADS>>>(ann, origin, bd, d, s, inc, bi, out, n);
}